// round 2
// baseline (speedup 1.0000x reference)
#include <cuda_runtime.h>
#include <cuda_bf16.h>
#include <cub/cub.cuh>
#include <cstdint>
#include <math.h>

typedef unsigned long long u64;
typedef unsigned int u32;

// ---------------------------------------------------------------------------
// Problem constants
// ---------------------------------------------------------------------------
#define NLVL 5
#define ATOT 261888          // total anchors per image
#define MCAND 21840          // total NMS candidates per image
#define POST_K 1000
#define NMS_T 0.7f
#define SCALE_CLAMP 4.135166556742356f
#define TOTHW 87296
#define MASK_PER_BATCH 3697344   // u32 words per batch
#define REM_WORDS 684

// output layout (float32)
#define OUT_KB   2618880
#define OUT_KS   2626880
#define OUT_VALID 2628880

__constant__ int c_COFF[5]  = {0, 6000, 12000, 18000, 21072};
__constant__ int c_K[5]     = {6000, 6000, 6000, 3072, 768};
__constant__ int c_W32[5]   = {188, 188, 188, 96, 24};
__constant__ int c_RWOFF[5] = {0, 188, 376, 564, 660};
__constant__ int c_MOFF[5]  = {0, 1128000, 2256000, 3384000, 3678912};
__constant__ int c_AOFF[5]  = {0, 196608, 245760, 258048, 261120};
__constant__ int c_LW[5]    = {256, 128, 64, 32, 16};
__constant__ int c_STR[5]   = {4, 8, 16, 32, 64};
__constant__ int c_SZ[5]    = {32, 64, 128, 256, 512};

// ---------------------------------------------------------------------------
// Static device scratch
// ---------------------------------------------------------------------------
__device__ float  g_t[2u * 256u * TOTHW];          // conv outputs (relu'd), [n][ci][TOTHW]
__device__ float2 g_wt2[589824];                   // transposed+duplicated conv weights
__device__ u64    g_keys[2 * ATOT];
__device__ u64    g_keyso[2 * ATOT];
__device__ float  g_boxes[2 * MCAND * 4];
__device__ float  g_scores[2 * MCAND];
__device__ u64    g_k2[2 * MCAND];
__device__ u64    g_k2o[2 * MCAND];
__device__ u32    g_mask[2u * MASK_PER_BATCH];
__device__ unsigned char g_cubtmp[48u * 1024u * 1024u];

__device__ __forceinline__ int lvl_of_c(int c) {
    return (c < 6000) ? 0 : (c < 12000) ? 1 : (c < 18000) ? 2 : (c < 21072) ? 3 : 4;
}
__device__ __forceinline__ int lvl_of_g(int g) {
    return (g < 196608) ? 0 : (g < 245760) ? 1 : (g < 258048) ? 2 : (g < 261120) ? 3 : 4;
}

// f32x2 helpers
__device__ __forceinline__ u64 pk(float lo, float hi) {
    u64 r; asm("mov.b64 %0, {%1,%2};" : "=l"(r) : "f"(lo), "f"(hi)); return r;
}
__device__ __forceinline__ float2 upk(u64 v) {
    float2 r; asm("mov.b64 {%0,%1}, %2;" : "=f"(r.x), "=f"(r.y) : "l"(v)); return r;
}
#define FMA2(d, a, b) asm("fma.rn.f32x2 %0, %1, %2, %0;" : "+l"(d) : "l"(a), "l"(b))

// ---------------------------------------------------------------------------
// Weight transpose: conv_w [co][ci][3][3] -> g_wt2[(ci*9+k)*256+co] = {w,w}
// ---------------------------------------------------------------------------
__global__ void wtrans_kernel(const float* __restrict__ w) {
    int i = blockIdx.x * 256 + threadIdx.x;
    if (i >= 589824) return;
    int co = i / 2304;
    int rem = i - co * 2304;       // ci*9 + k
    float v = w[i];
    g_wt2[(size_t)rem * 256 + co] = make_float2(v, v);
}

// ---------------------------------------------------------------------------
// 3x3 conv + bias + ReLU. Block 256 thr. Tile: 64 co x (8 rows x 16 cols).
// Per-thread: 4 co x 8 px (as 4 f32x2 pairs). grid z = n*4 + coTile.
// ---------------------------------------------------------------------------
__global__ __launch_bounds__(256, 2)
void conv3x3_kernel(const float* __restrict__ in, const float* __restrict__ bias,
                    int H, int W, int hwoff) {
    const int n = blockIdx.z >> 2;
    const int cobase = (blockIdx.z & 3) * 64;
    const int x0 = blockIdx.x * 16;
    const int y0 = blockIdx.y * 8;
    const int HW = H * W;
    const float* inb = in + (size_t)n * 256 * HW;

    __shared__ __align__(16) float2 Ws2[8 * 9 * 64];   // 36 KB
    __shared__ __align__(16) float  Xs[8][10][20];     // 6.25 KB (cols 0..17 used)

    const int tid = threadIdx.x;
    const int cg = tid & 15;
    const int pg = tid >> 4;
    const int row = pg >> 1;
    const int col8 = (pg & 1) * 8;

    u64 acc[4][4];
#pragma unroll
    for (int i = 0; i < 4; i++)
#pragma unroll
        for (int j = 0; j < 4; j++) acc[i][j] = 0ull;

    const u64* wp64 = (const u64*)Ws2;

#pragma unroll 1
    for (int ci0 = 0; ci0 < 256; ci0 += 8) {
        __syncthreads();
        // weights: 4608 float2 (8 ci x 9 k x 64 co)
        for (int i = tid; i < 4608; i += 256) {
            int ciq = i / 576;
            int rem = i - ciq * 576;      // k*64 + co'
            int k = rem >> 6, cop = rem & 63;
            Ws2[i] = g_wt2[(size_t)((ci0 + ciq) * 9 + k) * 256 + cobase + cop];
        }
        // input tile: 8 ci x 10 rows x 18 cols, zero-padded
        for (int i = tid; i < 1440; i += 256) {
            int ciq = i / 180;
            int rem = i - ciq * 180;
            int rr = rem / 18, cc = rem - rr * 18;
            int gy = y0 - 1 + rr, gx = x0 - 1 + cc;
            float v = 0.f;
            if (gy >= 0 && gy < H && gx >= 0 && gx < W)
                v = inb[(size_t)(ci0 + ciq) * HW + (size_t)gy * W + gx];
            Xs[ciq][rr][cc] = v;
        }
        __syncthreads();

#pragma unroll
        for (int ciq = 0; ciq < 8; ciq++) {
#pragma unroll
            for (int ky = 0; ky < 3; ky++) {
                const float* xr = &Xs[ciq][row + ky][col8];
                u64 pe0 = *(const u64*)(xr);
                u64 pe1 = *(const u64*)(xr + 2);
                u64 pe2 = *(const u64*)(xr + 4);
                u64 pe3 = *(const u64*)(xr + 6);
                u64 pe4 = *(const u64*)(xr + 8);
                float2 a0 = upk(pe0), a1 = upk(pe1), a2 = upk(pe2), a3 = upk(pe3), a4 = upk(pe4);
                u64 po0 = pk(a0.y, a1.x);
                u64 po1 = pk(a1.y, a2.x);
                u64 po2 = pk(a2.y, a3.x);
                u64 po3 = pk(a3.y, a4.x);
                const u64* wb = wp64 + (size_t)(ciq * 9 + ky * 3) * 64 + (cg << 2);
                // kx = 0
#pragma unroll
                for (int i = 0; i < 4; i++) {
                    u64 w = wb[i];
                    FMA2(acc[i][0], w, pe0); FMA2(acc[i][1], w, pe1);
                    FMA2(acc[i][2], w, pe2); FMA2(acc[i][3], w, pe3);
                }
                // kx = 1
#pragma unroll
                for (int i = 0; i < 4; i++) {
                    u64 w = wb[64 + i];
                    FMA2(acc[i][0], w, po0); FMA2(acc[i][1], w, po1);
                    FMA2(acc[i][2], w, po2); FMA2(acc[i][3], w, po3);
                }
                // kx = 2
#pragma unroll
                for (int i = 0; i < 4; i++) {
                    u64 w = wb[128 + i];
                    FMA2(acc[i][0], w, pe1); FMA2(acc[i][1], w, pe2);
                    FMA2(acc[i][2], w, pe3); FMA2(acc[i][3], w, pe4);
                }
            }
        }
    }

    // epilogue: bias + relu, write 4 co x 8 px
#pragma unroll
    for (int i = 0; i < 4; i++) {
        int co = cobase + (cg << 2) + i;
        float bv = bias[co];
        float2 v0 = upk(acc[i][0]), v1 = upk(acc[i][1]), v2 = upk(acc[i][2]), v3 = upk(acc[i][3]);
        float4 o1, o2;
        o1.x = fmaxf(v0.x + bv, 0.f); o1.y = fmaxf(v0.y + bv, 0.f);
        o1.z = fmaxf(v1.x + bv, 0.f); o1.w = fmaxf(v1.y + bv, 0.f);
        o2.x = fmaxf(v2.x + bv, 0.f); o2.y = fmaxf(v2.y + bv, 0.f);
        o2.z = fmaxf(v3.x + bv, 0.f); o2.w = fmaxf(v3.y + bv, 0.f);
        float* dst = g_t + (size_t)(n * 256 + co) * TOTHW + hwoff + (size_t)(y0 + row) * W + x0 + col8;
        *(float4*)dst = o1;
        *(float4*)(dst + 4) = o2;
    }
}

// ---------------------------------------------------------------------------
// 1x1 heads: 3 obj + 12 delta channels -> combined output [n][Atot][5]
// ---------------------------------------------------------------------------
__global__ __launch_bounds__(256)
void head_kernel(const float* __restrict__ ow, const float* __restrict__ ob,
                 const float* __restrict__ dw, const float* __restrict__ db,
                 float* __restrict__ out, int hwoff, int aoff) {
    __shared__ float sW[15 * 256];
    int tid = threadIdx.x;
    for (int i = tid; i < 3840; i += 256) {
        int k = i >> 8, ci = i & 255;
        sW[i] = (k < 3) ? ow[k * 256 + ci] : dw[(k - 3) * 256 + ci];
    }
    __syncthreads();
    int n = blockIdx.z;
    int hw = blockIdx.x * 256 + tid;
    const float* tp = g_t + (size_t)n * 256 * TOTHW + hwoff + hw;
    float acc[15];
#pragma unroll
    for (int k = 0; k < 15; k++) acc[k] = (k < 3) ? ob[k] : db[k - 3];
    for (int ci = 0; ci < 256; ci++) {
        float v = tp[(size_t)ci * TOTHW];
#pragma unroll
        for (int k = 0; k < 15; k++) acc[k] += v * sW[k * 256 + ci];
    }
    float* o = out + ((size_t)n * ATOT + aoff) * 5 + (size_t)hw * 15;
#pragma unroll
    for (int a = 0; a < 3; a++) {
        o[a * 5] = acc[a];
#pragma unroll
        for (int cc = 0; cc < 4; cc++) o[a * 5 + 1 + cc] = acc[3 + a * 4 + cc];
    }
}

// ---------------------------------------------------------------------------
// keys for per-level topk sort
// ---------------------------------------------------------------------------
__global__ void key1_kernel(const float* __restrict__ out) {
    int i = blockIdx.x * 256 + threadIdx.x;
    if (i >= 2 * ATOT) return;
    int n = i / ATOT, g = i - n * ATOT;
    int l = lvl_of_g(g);
    float sc = out[(size_t)(n * ATOT + g) * 5];
    u32 u = __float_as_uint(sc);
    u32 m = u ^ (((int)u < 0) ? 0xFFFFFFFFu : 0x80000000u);
    u32 inv = ~m;
    int idx = g - c_AOFF[l];
    g_keys[i] = ((u64)(u32)(n * 5 + l) << 50) | ((u64)inv << 18) | (u32)idx;
}

// ---------------------------------------------------------------------------
// gather candidates: decode + clip, build NMS order keys
// ---------------------------------------------------------------------------
__global__ void cand_kernel(const float* __restrict__ out) {
    int t = blockIdx.x * 256 + threadIdx.x;
    if (t >= 2 * MCAND) return;
    int n = t / MCAND, c = t - n * MCAND;
    int l = lvl_of_c(c);
    int r = c - c_COFF[l];
    u64 key = g_keyso[(size_t)n * ATOT + c_AOFF[l] + r];
    int idx = (int)(key & 0x3FFFFull);
    int a = idx % 3;
    int hw = idx / 3;
    int W = c_LW[l];
    int py = hw / W, px = hw - py * W;

    double ratio = (a == 0) ? 0.5 : (a == 1) ? 1.0 : 2.0;
    double sz = (double)c_SZ[l];
    double ws = sqrt(sz * sz / ratio);
    double hs = ws * ratio;
    double xx = (double)(px * c_STR[l]);
    double yy = (double)(py * c_STR[l]);
    float ax1 = (float)(xx - ws * 0.5), ay1 = (float)(yy - hs * 0.5);
    float ax2 = (float)(xx + ws * 0.5), ay2 = (float)(yy + hs * 0.5);

    float aw = ax2 - ax1, ah = ay2 - ay1;
    float acx = ax1 + 0.5f * aw, acy = ay1 + 0.5f * ah;
    const float* cmb = out + (size_t)(n * ATOT + c_AOFF[l] + idx) * 5;
    float sc = cmb[0];
    float dx = cmb[1], dy = cmb[2];
    float dwv = fminf(cmb[3], SCALE_CLAMP);
    float dhv = fminf(cmb[4], SCALE_CLAMP);
    float pcx = dx * aw + acx, pcy = dy * ah + acy;
    float pw = expf(dwv) * aw, ph = expf(dhv) * ah;
    float x1 = pcx - 0.5f * pw, y1 = pcy - 0.5f * ph;
    float x2 = pcx + 0.5f * pw, y2 = pcy + 0.5f * ph;
    x1 = fminf(fmaxf(x1, 0.f), 1024.f);
    y1 = fminf(fmaxf(y1, 0.f), 1024.f);
    x2 = fminf(fmaxf(x2, 0.f), 1024.f);
    y2 = fminf(fmaxf(y2, 0.f), 1024.f);

    float* bp = g_boxes + (size_t)t * 4;
    bp[0] = x1; bp[1] = y1; bp[2] = x2; bp[3] = y2;
    g_scores[t] = sc;

    u32 u = __float_as_uint(sc);
    u32 m = u ^ (((int)u < 0) ? 0xFFFFFFFFu : 0x80000000u);
    u32 inv = ~m;
    g_k2[t] = ((u64)(u32)n << 47) | ((u64)inv << 15) | (u32)c;
}

// ---------------------------------------------------------------------------
// NMS suppression bitmask (level-block-diagonal, upper triangle, offset boxes)
// ---------------------------------------------------------------------------
__global__ __launch_bounds__(128)
void mask_kernel(int l) {
    int K = c_K[l], Wn = c_W32[l];
    int cb = blockIdx.x * 128, rb = blockIdx.y * 128;
    if (rb > cb + 127) return;
    int b = blockIdx.z;
    int tid = threadIdx.x;
    __shared__ float4 sB[128];
    __shared__ float sA[128];
    float off = (float)l * 2000.0f;

    int cc = cb + tid;
    if (cc < K) {
        const float* bp = g_boxes + ((size_t)b * MCAND + c_COFF[l] + cc) * 4;
        float4 v = make_float4(bp[0] + off, bp[1] + off, bp[2] + off, bp[3] + off);
        sB[tid] = v;
        sA[tid] = (v.z - v.x) * (v.w - v.y);
    }
    __syncthreads();
    int r = rb + tid;
    if (r >= K) return;
    const float* rp = g_boxes + ((size_t)b * MCAND + c_COFF[l] + r) * 4;
    float rx1 = rp[0] + off, ry1 = rp[1] + off, rx2 = rp[2] + off, ry2 = rp[3] + off;
    float ra = (rx2 - rx1) * (ry2 - ry1);
    u32 wds[4] = {0, 0, 0, 0};
    int jmax = min(128, K - cb);
    for (int j = 0; j < jmax; j++) {
        int c2 = cb + j;
        if (c2 <= r) continue;
        float4 o = sB[j];
        float x1 = fmaxf(rx1, o.x), y1 = fmaxf(ry1, o.y);
        float x2 = fminf(rx2, o.z), y2 = fminf(ry2, o.w);
        float inter = fmaxf(x2 - x1, 0.f) * fmaxf(y2 - y1, 0.f);
        float iou = inter / (ra + sA[j] - inter + 1e-9f);
        if (iou > NMS_T) wds[j >> 5] |= 1u << (j & 31);
    }
    u32* dst = g_mask + (size_t)b * MASK_PER_BATCH + c_MOFF[l] + (size_t)r * Wn + (cb >> 5);
#pragma unroll
    for (int w2 = 0; w2 < 4; w2++)
        if ((cb >> 5) + w2 < Wn) dst[w2] = wds[w2];
}

// ---------------------------------------------------------------------------
// Greedy scan: 1 warp per batch, removed-bitmap in smem, ballot skip
// ---------------------------------------------------------------------------
__global__ __launch_bounds__(32)
void scan_kernel(float* __restrict__ out) {
    int b = blockIdx.x;
    int lane = threadIdx.x;
    __shared__ u32 rem[REM_WORDS];
    for (int i = lane; i < REM_WORDS; i += 32) rem[i] = 0;
    __syncwarp();

    const u64* ord = g_k2o + (size_t)b * MCAND;
    int p = 0, kept = 0;
    while (p < MCAND && kept < POST_K) {
        int rank = p + lane;
        int c = -1;
        bool fr = false;
        if (rank < MCAND) {
            c = (int)(ord[rank] & 0x7FFFull);
            int l = lvl_of_c(c);
            int rl = c - c_COFF[l];
            fr = !((rem[c_RWOFF[l] + (rl >> 5)] >> (rl & 31)) & 1u);
        }
        u32 fm = __ballot_sync(0xffffffffu, fr);
        if (!fm) { p += 32; continue; }
        int tt = __ffs(fm) - 1;
        int ck = __shfl_sync(0xffffffffu, c, tt);
        int l = lvl_of_c(ck);
        int rl = ck - c_COFF[l];
        int Wn = c_W32[l];
        const u32* rowp = g_mask + (size_t)b * MASK_PER_BATCH + c_MOFF[l] + (size_t)rl * Wn;
        for (int w = lane; w < Wn; w += 32) rem[c_RWOFF[l] + w] |= rowp[w];
        if (lane == 0) {
            const float* bx = g_boxes + ((size_t)b * MCAND + ck) * 4;
            float* kb = out + OUT_KB + ((size_t)b * POST_K + kept) * 4;
            kb[0] = bx[0]; kb[1] = bx[1]; kb[2] = bx[2]; kb[3] = bx[3];
            out[OUT_KS + b * POST_K + kept] = g_scores[(size_t)b * MCAND + ck];
            out[OUT_VALID + b * POST_K + kept] = 1.0f;
        }
        __syncwarp();
        kept++;
        p = p + tt + 1;
    }
    // exhaustion fill: reference yields idx=0 -> boxes[0], scores[0], valid=0
    const float* bx0 = g_boxes + (size_t)b * MCAND * 4;
    float s0 = g_scores[(size_t)b * MCAND];
    for (int k2 = kept + lane; k2 < POST_K; k2 += 32) {
        float* kb = out + OUT_KB + ((size_t)b * POST_K + k2) * 4;
        kb[0] = bx0[0]; kb[1] = bx0[1]; kb[2] = bx0[2]; kb[3] = bx0[3];
        out[OUT_KS + b * POST_K + k2] = s0;
        out[OUT_VALID + b * POST_K + k2] = 0.0f;
    }
}

// ---------------------------------------------------------------------------
// Host launcher
// ---------------------------------------------------------------------------
extern "C" void kernel_launch(void* const* d_in, const int* in_sizes, int n_in,
                              void* d_out, int out_size) {
    const float* f[5];
    for (int i = 0; i < 5; i++) f[i] = (const float*)d_in[i];
    const float* conv_w = (const float*)d_in[5];
    const float* conv_b = (const float*)d_in[6];
    const float* obj_w  = (const float*)d_in[7];
    const float* obj_b  = (const float*)d_in[8];
    const float* del_w  = (const float*)d_in[9];
    const float* del_b  = (const float*)d_in[10];
    float* out = (float*)d_out;

    static const int hH[5] = {256, 128, 64, 32, 16};
    static const int hW[5] = {256, 128, 64, 32, 16};
    static const int hHW[5] = {65536, 16384, 4096, 1024, 256};
    static const int hHWOFF[5] = {0, 65536, 81920, 86016, 87040};
    static const int hAOFF[5] = {0, 196608, 245760, 258048, 261120};
    static const int hT[5] = {47, 47, 47, 24, 6};

    void *p_keys, *p_keyso, *p_k2, *p_k2o, *p_mask, *p_tmp;
    cudaGetSymbolAddress(&p_keys, g_keys);
    cudaGetSymbolAddress(&p_keyso, g_keyso);
    cudaGetSymbolAddress(&p_k2, g_k2);
    cudaGetSymbolAddress(&p_k2o, g_k2o);
    cudaGetSymbolAddress(&p_mask, g_mask);
    cudaGetSymbolAddress(&p_tmp, g_cubtmp);

    wtrans_kernel<<<2304, 256>>>(conv_w);

    for (int l = 0; l < 5; l++) {
        dim3 g(hW[l] / 16, hH[l] / 8, 8);
        conv3x3_kernel<<<g, 256>>>(f[l], conv_b, hH[l], hW[l], hHWOFF[l]);
    }
    for (int l = 0; l < 5; l++) {
        dim3 g(hHW[l] / 256, 1, 2);
        head_kernel<<<g, 256>>>(obj_w, obj_b, del_w, del_b, out, hHWOFF[l], hAOFF[l]);
    }

    key1_kernel<<<(2 * ATOT) / 256, 256>>>(out);
    {
        size_t tb = sizeof(g_cubtmp);
        cub::DeviceRadixSort::SortKeys(p_tmp, tb, (const u64*)p_keys, (u64*)p_keyso,
                                       2 * ATOT, 0, 54);
    }

    cand_kernel<<<(2 * MCAND + 255) / 256, 256>>>(out);
    {
        size_t tb = sizeof(g_cubtmp);
        cub::DeviceRadixSort::SortKeys(p_tmp, tb, (const u64*)p_k2, (u64*)p_k2o,
                                       2 * MCAND, 0, 48);
    }

    cudaMemsetAsync(p_mask, 0, (size_t)2 * MASK_PER_BATCH * sizeof(u32));
    for (int l = 0; l < 5; l++) {
        dim3 g(hT[l], hT[l], 2);
        mask_kernel<<<g, 128>>>(l);
    }

    scan_kernel<<<2, 32>>>(out);
}

// round 3
// speedup vs baseline: 1.2327x; 1.2327x over previous
#include <cuda_runtime.h>
#include <cuda_bf16.h>
#include <cub/cub.cuh>
#include <cstdint>
#include <math.h>

typedef unsigned long long u64;
typedef unsigned int u32;

// ---------------------------------------------------------------------------
// Problem constants
// ---------------------------------------------------------------------------
#define NLVL 5
#define ATOT 261888          // total anchors per image
#define MCAND 21840          // total NMS candidates per image
#define POST_K 1000
#define NMS_T 0.7f
#define SCALE_CLAMP 4.135166556742356f
#define TOTHW 87296
#define MASK_PER_BATCH 3697344   // u32 words per batch
#define REM_WORDS 684

// output layout (float32)
#define OUT_KB   2618880
#define OUT_KS   2626880
#define OUT_VALID 2628880

__constant__ int c_COFF[5]  = {0, 6000, 12000, 18000, 21072};
__constant__ int c_K[5]     = {6000, 6000, 6000, 3072, 768};
__constant__ int c_W32[5]   = {188, 188, 188, 96, 24};
__constant__ int c_RWOFF[5] = {0, 188, 376, 564, 660};
__constant__ int c_MOFF[5]  = {0, 1128000, 2256000, 3384000, 3678912};
__constant__ int c_AOFF[5]  = {0, 196608, 245760, 258048, 261120};
__constant__ int c_LW[5]    = {256, 128, 64, 32, 16};
__constant__ int c_STR[5]   = {4, 8, 16, 32, 64};
__constant__ int c_SZ[5]    = {32, 64, 128, 256, 512};

// ---------------------------------------------------------------------------
// Static device scratch
// ---------------------------------------------------------------------------
__device__ float  g_t[2u * 256u * TOTHW];          // conv outputs (relu'd), [n][ci][TOTHW]
// weights, conv-kernel-ready layout:
// [coTile t][ci*9+k][i][cg] as float2 (duplicated pair), linear index
//   ((t*2304 + ci*9 + k)*4 + i)*16 + cg
__device__ float2 g_wt2[589824];
__device__ u64    g_keys[2 * ATOT];
__device__ u64    g_keyso[2 * ATOT];
__device__ float  g_boxes[2 * MCAND * 4];
__device__ float  g_scores[2 * MCAND];
__device__ u64    g_k2[2 * MCAND];
__device__ u64    g_k2o[2 * MCAND];
__device__ u32    g_mask[2u * MASK_PER_BATCH];
__device__ unsigned char g_cubtmp[48u * 1024u * 1024u];

__device__ __forceinline__ int lvl_of_c(int c) {
    return (c < 6000) ? 0 : (c < 12000) ? 1 : (c < 18000) ? 2 : (c < 21072) ? 3 : 4;
}
__device__ __forceinline__ int lvl_of_g(int g) {
    return (g < 196608) ? 0 : (g < 245760) ? 1 : (g < 258048) ? 2 : (g < 261120) ? 3 : 4;
}

// f32x2 helpers
__device__ __forceinline__ u64 pk(float lo, float hi) {
    u64 r; asm("mov.b64 %0, {%1,%2};" : "=l"(r) : "f"(lo), "f"(hi)); return r;
}
__device__ __forceinline__ float2 upk(u64 v) {
    float2 r; asm("mov.b64 {%0,%1}, %2;" : "=f"(r.x), "=f"(r.y) : "l"(v)); return r;
}
#define FMA2(d, a, b) asm("fma.rn.f32x2 %0, %1, %2, %0;" : "+l"(d) : "l"(a), "l"(b))

// ---------------------------------------------------------------------------
// Weight transpose: conv_w [co][ci][3][3] -> conv-ready layout (see g_wt2)
// co = t*64 + cg*4 + i
// ---------------------------------------------------------------------------
__global__ void wtrans_kernel(const float* __restrict__ w) {
    int idx = blockIdx.x * 256 + threadIdx.x;
    if (idx >= 589824) return;
    int co = idx / 2304;
    int rem = idx - co * 2304;       // ci*9 + k
    float v = w[idx];
    int t = co >> 6;
    int cg = (co & 63) >> 2;
    int i = co & 3;
    g_wt2[(size_t)((t * 2304 + rem) * 4 + i) * 16 + cg] = make_float2(v, v);
}

// ---------------------------------------------------------------------------
// 3x3 conv + bias + ReLU. Block 256 thr. Tile: 64 co x (8 rows x 16 cols).
// Per-thread: 4 co x 8 px (4 f32x2 pairs). grid z = n*4 + coTile.
// Weight smem layout has cg innermost -> conflict-free LDS64 (128B/load).
// ---------------------------------------------------------------------------
__global__ __launch_bounds__(256, 2)
void conv3x3_kernel(const float* __restrict__ in, const float* __restrict__ bias,
                    int H, int W, int hwoff) {
    const int n = blockIdx.z >> 2;
    const int cot = blockIdx.z & 3;
    const int cobase = cot * 64;
    const int x0 = blockIdx.x * 16;
    const int y0 = blockIdx.y * 8;
    const int HW = H * W;
    const float* inb = in + (size_t)n * 256 * HW;

    __shared__ __align__(16) float2 Ws2[8 * 9 * 64];   // 36 KB, [ciq][k][i][cg]
    __shared__ __align__(16) float  Xs[8][10][20];     // 6.25 KB (cols 0..17 used)

    const int tid = threadIdx.x;
    const int cg = tid & 15;
    const int pg = tid >> 4;
    const int row = pg >> 1;
    const int col8 = (pg & 1) * 8;

    u64 acc[4][4];
#pragma unroll
    for (int i = 0; i < 4; i++)
#pragma unroll
        for (int j = 0; j < 4; j++) acc[i][j] = 0ull;

    const u64* wp64 = (const u64*)Ws2;
    // per-ci0 weight source: contiguous 4608-float2 block
    const float2* wsrc_base = g_wt2 + (size_t)cot * 2304 * 64;

#pragma unroll 1
    for (int ci0 = 0; ci0 < 256; ci0 += 8) {
        __syncthreads();
        // weights: contiguous, fully coalesced copy of 4608 float2
        {
            const float2* src = wsrc_base + (size_t)ci0 * 9 * 64;
            for (int i = tid; i < 4608; i += 256) Ws2[i] = src[i];
        }
        // input tile: 8 ci x 10 rows x 18 cols, zero-padded
        for (int i = tid; i < 1440; i += 256) {
            int ciq = i / 180;
            int rem = i - ciq * 180;
            int rr = rem / 18, cc = rem - rr * 18;
            int gy = y0 - 1 + rr, gx = x0 - 1 + cc;
            float v = 0.f;
            if (gy >= 0 && gy < H && gx >= 0 && gx < W)
                v = inb[(size_t)(ci0 + ciq) * HW + (size_t)gy * W + gx];
            Xs[ciq][rr][cc] = v;
        }
        __syncthreads();

#pragma unroll
        for (int ciq = 0; ciq < 8; ciq++) {
#pragma unroll
            for (int ky = 0; ky < 3; ky++) {
                const float* xr = &Xs[ciq][row + ky][col8];
                u64 pe0 = *(const u64*)(xr);
                u64 pe1 = *(const u64*)(xr + 2);
                u64 pe2 = *(const u64*)(xr + 4);
                u64 pe3 = *(const u64*)(xr + 6);
                u64 pe4 = *(const u64*)(xr + 8);
                float2 a0 = upk(pe0), a1 = upk(pe1), a2 = upk(pe2), a3 = upk(pe3), a4 = upk(pe4);
                u64 po0 = pk(a0.y, a1.x);
                u64 po1 = pk(a1.y, a2.x);
                u64 po2 = pk(a2.y, a3.x);
                u64 po3 = pk(a3.y, a4.x);
                // weight index: ((ciq*9 + ky*3 + kx)*4 + i)*16 + cg
                const u64* wb = wp64 + (size_t)(ciq * 9 + ky * 3) * 64 + cg;
                // kx = 0
#pragma unroll
                for (int i = 0; i < 4; i++) {
                    u64 w = wb[i * 16];
                    FMA2(acc[i][0], w, pe0); FMA2(acc[i][1], w, pe1);
                    FMA2(acc[i][2], w, pe2); FMA2(acc[i][3], w, pe3);
                }
                // kx = 1
#pragma unroll
                for (int i = 0; i < 4; i++) {
                    u64 w = wb[64 + i * 16];
                    FMA2(acc[i][0], w, po0); FMA2(acc[i][1], w, po1);
                    FMA2(acc[i][2], w, po2); FMA2(acc[i][3], w, po3);
                }
                // kx = 2
#pragma unroll
                for (int i = 0; i < 4; i++) {
                    u64 w = wb[128 + i * 16];
                    FMA2(acc[i][0], w, pe1); FMA2(acc[i][1], w, pe2);
                    FMA2(acc[i][2], w, pe3); FMA2(acc[i][3], w, pe4);
                }
            }
        }
    }

    // epilogue: bias + relu, write 4 co x 8 px
#pragma unroll
    for (int i = 0; i < 4; i++) {
        int co = cobase + cg * 4 + i;
        float bv = bias[co];
        float2 v0 = upk(acc[i][0]), v1 = upk(acc[i][1]), v2 = upk(acc[i][2]), v3 = upk(acc[i][3]);
        float4 o1, o2;
        o1.x = fmaxf(v0.x + bv, 0.f); o1.y = fmaxf(v0.y + bv, 0.f);
        o1.z = fmaxf(v1.x + bv, 0.f); o1.w = fmaxf(v1.y + bv, 0.f);
        o2.x = fmaxf(v2.x + bv, 0.f); o2.y = fmaxf(v2.y + bv, 0.f);
        o2.z = fmaxf(v3.x + bv, 0.f); o2.w = fmaxf(v3.y + bv, 0.f);
        float* dst = g_t + (size_t)(n * 256 + co) * TOTHW + hwoff + (size_t)(y0 + row) * W + x0 + col8;
        *(float4*)dst = o1;
        *(float4*)(dst + 4) = o2;
    }
}

// ---------------------------------------------------------------------------
// 1x1 heads: 3 obj + 12 delta channels -> combined output [n][Atot][5]
// ---------------------------------------------------------------------------
__global__ __launch_bounds__(256)
void head_kernel(const float* __restrict__ ow, const float* __restrict__ ob,
                 const float* __restrict__ dw, const float* __restrict__ db,
                 float* __restrict__ out, int hwoff, int aoff) {
    __shared__ float sW[15 * 256];
    int tid = threadIdx.x;
    for (int i = tid; i < 3840; i += 256) {
        int k = i >> 8, ci = i & 255;
        sW[i] = (k < 3) ? ow[k * 256 + ci] : dw[(k - 3) * 256 + ci];
    }
    __syncthreads();
    int n = blockIdx.z;
    int hw = blockIdx.x * 256 + tid;
    const float* tp = g_t + (size_t)n * 256 * TOTHW + hwoff + hw;
    float acc[15];
#pragma unroll
    for (int k = 0; k < 15; k++) acc[k] = (k < 3) ? ob[k] : db[k - 3];
    for (int ci = 0; ci < 256; ci++) {
        float v = tp[(size_t)ci * TOTHW];
#pragma unroll
        for (int k = 0; k < 15; k++) acc[k] += v * sW[k * 256 + ci];
    }
    float* o = out + ((size_t)n * ATOT + aoff) * 5 + (size_t)hw * 15;
#pragma unroll
    for (int a = 0; a < 3; a++) {
        o[a * 5] = acc[a];
#pragma unroll
        for (int cc = 0; cc < 4; cc++) o[a * 5 + 1 + cc] = acc[3 + a * 4 + cc];
    }
}

// ---------------------------------------------------------------------------
// keys for per-level topk sort
// ---------------------------------------------------------------------------
__global__ void key1_kernel(const float* __restrict__ out) {
    int i = blockIdx.x * 256 + threadIdx.x;
    if (i >= 2 * ATOT) return;
    int n = i / ATOT, g = i - n * ATOT;
    int l = lvl_of_g(g);
    float sc = out[(size_t)(n * ATOT + g) * 5];
    u32 u = __float_as_uint(sc);
    u32 m = u ^ (((int)u < 0) ? 0xFFFFFFFFu : 0x80000000u);
    u32 inv = ~m;
    int idx = g - c_AOFF[l];
    g_keys[i] = ((u64)(u32)(n * 5 + l) << 50) | ((u64)inv << 18) | (u32)idx;
}

// ---------------------------------------------------------------------------
// gather candidates: decode + clip, build NMS order keys
// ---------------------------------------------------------------------------
__global__ void cand_kernel(const float* __restrict__ out) {
    int t = blockIdx.x * 256 + threadIdx.x;
    if (t >= 2 * MCAND) return;
    int n = t / MCAND, c = t - n * MCAND;
    int l = lvl_of_c(c);
    int r = c - c_COFF[l];
    u64 key = g_keyso[(size_t)n * ATOT + c_AOFF[l] + r];
    int idx = (int)(key & 0x3FFFFull);
    int a = idx % 3;
    int hw = idx / 3;
    int W = c_LW[l];
    int py = hw / W, px = hw - py * W;

    double ratio = (a == 0) ? 0.5 : (a == 1) ? 1.0 : 2.0;
    double sz = (double)c_SZ[l];
    double ws = sqrt(sz * sz / ratio);
    double hs = ws * ratio;
    double xx = (double)(px * c_STR[l]);
    double yy = (double)(py * c_STR[l]);
    float ax1 = (float)(xx - ws * 0.5), ay1 = (float)(yy - hs * 0.5);
    float ax2 = (float)(xx + ws * 0.5), ay2 = (float)(yy + hs * 0.5);

    float aw = ax2 - ax1, ah = ay2 - ay1;
    float acx = ax1 + 0.5f * aw, acy = ay1 + 0.5f * ah;
    const float* cmb = out + (size_t)(n * ATOT + c_AOFF[l] + idx) * 5;
    float sc = cmb[0];
    float dx = cmb[1], dy = cmb[2];
    float dwv = fminf(cmb[3], SCALE_CLAMP);
    float dhv = fminf(cmb[4], SCALE_CLAMP);
    float pcx = dx * aw + acx, pcy = dy * ah + acy;
    float pw = expf(dwv) * aw, ph = expf(dhv) * ah;
    float x1 = pcx - 0.5f * pw, y1 = pcy - 0.5f * ph;
    float x2 = pcx + 0.5f * pw, y2 = pcy + 0.5f * ph;
    x1 = fminf(fmaxf(x1, 0.f), 1024.f);
    y1 = fminf(fmaxf(y1, 0.f), 1024.f);
    x2 = fminf(fmaxf(x2, 0.f), 1024.f);
    y2 = fminf(fmaxf(y2, 0.f), 1024.f);

    float* bp = g_boxes + (size_t)t * 4;
    bp[0] = x1; bp[1] = y1; bp[2] = x2; bp[3] = y2;
    g_scores[t] = sc;

    u32 u = __float_as_uint(sc);
    u32 m = u ^ (((int)u < 0) ? 0xFFFFFFFFu : 0x80000000u);
    u32 inv = ~m;
    g_k2[t] = ((u64)(u32)n << 47) | ((u64)inv << 15) | (u32)c;
}

// ---------------------------------------------------------------------------
// NMS suppression bitmask (level-block-diagonal, upper triangle, offset boxes)
// ---------------------------------------------------------------------------
__global__ __launch_bounds__(128)
void mask_kernel(int l) {
    int K = c_K[l], Wn = c_W32[l];
    int cb = blockIdx.x * 128, rb = blockIdx.y * 128;
    if (rb > cb + 127) return;
    int b = blockIdx.z;
    int tid = threadIdx.x;
    __shared__ float4 sB[128];
    __shared__ float sA[128];
    float off = (float)l * 2000.0f;

    int cc = cb + tid;
    if (cc < K) {
        const float* bp = g_boxes + ((size_t)b * MCAND + c_COFF[l] + cc) * 4;
        float4 v = make_float4(bp[0] + off, bp[1] + off, bp[2] + off, bp[3] + off);
        sB[tid] = v;
        sA[tid] = (v.z - v.x) * (v.w - v.y);
    }
    __syncthreads();
    int r = rb + tid;
    if (r >= K) return;
    const float* rp = g_boxes + ((size_t)b * MCAND + c_COFF[l] + r) * 4;
    float rx1 = rp[0] + off, ry1 = rp[1] + off, rx2 = rp[2] + off, ry2 = rp[3] + off;
    float ra = (rx2 - rx1) * (ry2 - ry1);
    u32 wds[4] = {0, 0, 0, 0};
    int jmax = min(128, K - cb);
    for (int j = 0; j < jmax; j++) {
        int c2 = cb + j;
        if (c2 <= r) continue;
        float4 o = sB[j];
        float x1 = fmaxf(rx1, o.x), y1 = fmaxf(ry1, o.y);
        float x2 = fminf(rx2, o.z), y2 = fminf(ry2, o.w);
        float inter = fmaxf(x2 - x1, 0.f) * fmaxf(y2 - y1, 0.f);
        float iou = inter / (ra + sA[j] - inter + 1e-9f);
        if (iou > NMS_T) wds[j >> 5] |= 1u << (j & 31);
    }
    u32* dst = g_mask + (size_t)b * MASK_PER_BATCH + c_MOFF[l] + (size_t)r * Wn + (cb >> 5);
#pragma unroll
    for (int w2 = 0; w2 < 4; w2++)
        if ((cb >> 5) + w2 < Wn) dst[w2] = wds[w2];
}

// ---------------------------------------------------------------------------
// Greedy scan: 1 warp per batch, removed-bitmap in smem, ballot skip
// ---------------------------------------------------------------------------
__global__ __launch_bounds__(32)
void scan_kernel(float* __restrict__ out) {
    int b = blockIdx.x;
    int lane = threadIdx.x;
    __shared__ u32 rem[REM_WORDS];
    for (int i = lane; i < REM_WORDS; i += 32) rem[i] = 0;
    __syncwarp();

    const u64* ord = g_k2o + (size_t)b * MCAND;
    int p = 0, kept = 0;
    while (p < MCAND && kept < POST_K) {
        int rank = p + lane;
        int c = -1;
        bool fr = false;
        if (rank < MCAND) {
            c = (int)(ord[rank] & 0x7FFFull);
            int l = lvl_of_c(c);
            int rl = c - c_COFF[l];
            fr = !((rem[c_RWOFF[l] + (rl >> 5)] >> (rl & 31)) & 1u);
        }
        u32 fm = __ballot_sync(0xffffffffu, fr);
        if (!fm) { p += 32; continue; }
        int tt = __ffs(fm) - 1;
        int ck = __shfl_sync(0xffffffffu, c, tt);
        int l = lvl_of_c(ck);
        int rl = ck - c_COFF[l];
        int Wn = c_W32[l];
        const u32* rowp = g_mask + (size_t)b * MASK_PER_BATCH + c_MOFF[l] + (size_t)rl * Wn;
        for (int w = lane; w < Wn; w += 32) rem[c_RWOFF[l] + w] |= rowp[w];
        if (lane == 0) {
            const float* bx = g_boxes + ((size_t)b * MCAND + ck) * 4;
            float* kb = out + OUT_KB + ((size_t)b * POST_K + kept) * 4;
            kb[0] = bx[0]; kb[1] = bx[1]; kb[2] = bx[2]; kb[3] = bx[3];
            out[OUT_KS + b * POST_K + kept] = g_scores[(size_t)b * MCAND + ck];
            out[OUT_VALID + b * POST_K + kept] = 1.0f;
        }
        __syncwarp();
        kept++;
        p = p + tt + 1;
    }
    // exhaustion fill: reference yields idx=0 -> boxes[0], scores[0], valid=0
    const float* bx0 = g_boxes + (size_t)b * MCAND * 4;
    float s0 = g_scores[(size_t)b * MCAND];
    for (int k2 = kept + lane; k2 < POST_K; k2 += 32) {
        float* kb = out + OUT_KB + ((size_t)b * POST_K + k2) * 4;
        kb[0] = bx0[0]; kb[1] = bx0[1]; kb[2] = bx0[2]; kb[3] = bx0[3];
        out[OUT_KS + b * POST_K + k2] = s0;
        out[OUT_VALID + b * POST_K + k2] = 0.0f;
    }
}

// ---------------------------------------------------------------------------
// Host launcher
// ---------------------------------------------------------------------------
extern "C" void kernel_launch(void* const* d_in, const int* in_sizes, int n_in,
                              void* d_out, int out_size) {
    const float* f[5];
    for (int i = 0; i < 5; i++) f[i] = (const float*)d_in[i];
    const float* conv_w = (const float*)d_in[5];
    const float* conv_b = (const float*)d_in[6];
    const float* obj_w  = (const float*)d_in[7];
    const float* obj_b  = (const float*)d_in[8];
    const float* del_w  = (const float*)d_in[9];
    const float* del_b  = (const float*)d_in[10];
    float* out = (float*)d_out;

    static const int hH[5] = {256, 128, 64, 32, 16};
    static const int hW[5] = {256, 128, 64, 32, 16};
    static const int hHW[5] = {65536, 16384, 4096, 1024, 256};
    static const int hHWOFF[5] = {0, 65536, 81920, 86016, 87040};
    static const int hAOFF[5] = {0, 196608, 245760, 258048, 261120};
    static const int hT[5] = {47, 47, 47, 24, 6};

    void *p_keys, *p_keyso, *p_k2, *p_k2o, *p_mask, *p_tmp;
    cudaGetSymbolAddress(&p_keys, g_keys);
    cudaGetSymbolAddress(&p_keyso, g_keyso);
    cudaGetSymbolAddress(&p_k2, g_k2);
    cudaGetSymbolAddress(&p_k2o, g_k2o);
    cudaGetSymbolAddress(&p_mask, g_mask);
    cudaGetSymbolAddress(&p_tmp, g_cubtmp);

    wtrans_kernel<<<2304, 256>>>(conv_w);

    for (int l = 0; l < 5; l++) {
        dim3 g(hW[l] / 16, hH[l] / 8, 8);
        conv3x3_kernel<<<g, 256>>>(f[l], conv_b, hH[l], hW[l], hHWOFF[l]);
    }
    for (int l = 0; l < 5; l++) {
        dim3 g(hHW[l] / 256, 1, 2);
        head_kernel<<<g, 256>>>(obj_w, obj_b, del_w, del_b, out, hHWOFF[l], hAOFF[l]);
    }

    key1_kernel<<<(2 * ATOT) / 256, 256>>>(out);
    {
        size_t tb = sizeof(g_cubtmp);
        cub::DeviceRadixSort::SortKeys(p_tmp, tb, (const u64*)p_keys, (u64*)p_keyso,
                                       2 * ATOT, 0, 54);
    }

    cand_kernel<<<(2 * MCAND + 255) / 256, 256>>>(out);
    {
        size_t tb = sizeof(g_cubtmp);
        cub::DeviceRadixSort::SortKeys(p_tmp, tb, (const u64*)p_k2, (u64*)p_k2o,
                                       2 * MCAND, 0, 48);
    }

    cudaMemsetAsync(p_mask, 0, (size_t)2 * MASK_PER_BATCH * sizeof(u32));
    for (int l = 0; l < 5; l++) {
        dim3 g(hT[l], hT[l], 2);
        mask_kernel<<<g, 128>>>(l);
    }

    scan_kernel<<<2, 32>>>(out);
}

// round 4
// speedup vs baseline: 1.5619x; 1.2671x over previous
#include <cuda_runtime.h>
#include <cuda_bf16.h>
#include <cub/cub.cuh>
#include <cstdint>
#include <math.h>

typedef unsigned long long u64;
typedef unsigned int u32;

// ---------------------------------------------------------------------------
// Problem constants
// ---------------------------------------------------------------------------
#define NLVL 5
#define ATOT 261888          // total anchors per image
#define MCAND 21840          // total NMS candidates per image
#define POST_K 1000
#define NMS_T 0.7f
#define SCALE_CLAMP 4.135166556742356f
#define TOTHW 87296
#define MASK_PER_BATCH 3697344   // u32 words per batch
#define REM_WORDS 684

// output layout (float32)
#define OUT_KB   2618880
#define OUT_KS   2626880
#define OUT_VALID 2628880

__constant__ int c_COFF[5]  = {0, 6000, 12000, 18000, 21072};
__constant__ int c_K[5]     = {6000, 6000, 6000, 3072, 768};
__constant__ int c_W32[5]   = {188, 188, 188, 96, 24};
__constant__ int c_RWOFF[5] = {0, 188, 376, 564, 660};
__constant__ int c_MOFF[5]  = {0, 1128000, 2256000, 3384000, 3678912};
__constant__ int c_AOFF[5]  = {0, 196608, 245760, 258048, 261120};
__constant__ int c_LW[5]    = {256, 128, 64, 32, 16};
__constant__ int c_STR[5]   = {4, 8, 16, 32, 64};
__constant__ int c_SZ[5]    = {32, 64, 128, 256, 512};

// fused-conv tile table
__constant__ int c_TS[6]    = {0, 256, 320, 336, 340, 342}; // tile start per level
__constant__ int c_TC[5]    = {8, 4, 2, 1, 1};              // tile cols per level
__constant__ int c_HWOFF[5] = {0, 65536, 81920, 86016, 87040};

// ---------------------------------------------------------------------------
// Static device scratch
// ---------------------------------------------------------------------------
__device__ float  g_t[2u * 256u * TOTHW];          // conv outputs (relu'd), [n][ci][TOTHW]
// weights, conv-kernel-ready layout:
// [coTile t][ci*9+k][i][cg] as float2 (duplicated pair)
__device__ float2 g_wt2[589824];
__device__ u64    g_keys[2 * ATOT];
__device__ u64    g_keyso[2 * ATOT];
__device__ float  g_boxes[2 * MCAND * 4];
__device__ float  g_scores[2 * MCAND];
__device__ u64    g_k2[2 * MCAND];
__device__ u64    g_k2o[2 * MCAND];
__device__ u32    g_mask[2u * MASK_PER_BATCH];
__device__ unsigned char g_cubtmp[48u * 1024u * 1024u];

__device__ __forceinline__ int lvl_of_c(int c) {
    return (c < 6000) ? 0 : (c < 12000) ? 1 : (c < 18000) ? 2 : (c < 21072) ? 3 : 4;
}
__device__ __forceinline__ int lvl_of_g(int g) {
    return (g < 196608) ? 0 : (g < 245760) ? 1 : (g < 258048) ? 2 : (g < 261120) ? 3 : 4;
}

// f32x2 helpers
__device__ __forceinline__ u64 pk(float lo, float hi) {
    u64 r; asm("mov.b64 %0, {%1,%2};" : "=l"(r) : "f"(lo), "f"(hi)); return r;
}
__device__ __forceinline__ float2 upk(u64 v) {
    float2 r; asm("mov.b64 {%0,%1}, %2;" : "=f"(r.x), "=f"(r.y) : "l"(v)); return r;
}
#define FMA2(d, a, b) asm("fma.rn.f32x2 %0, %1, %2, %0;" : "+l"(d) : "l"(a), "l"(b))

// cp.async helpers
__device__ __forceinline__ u32 s2u(const void* p) { return (u32)__cvta_generic_to_shared(p); }
__device__ __forceinline__ void cpa8(u32 d, const void* s) {
    asm volatile("cp.async.ca.shared.global [%0], [%1], 8;" :: "r"(d), "l"(s));
}
__device__ __forceinline__ void cpa4z(u32 d, const void* s, int sz) {
    asm volatile("cp.async.ca.shared.global [%0], [%1], 4, %2;" :: "r"(d), "l"(s), "r"(sz));
}
#define CPA_COMMIT() asm volatile("cp.async.commit_group;")
#define CPA_WAIT1()  asm volatile("cp.async.wait_group 1;")

// ---------------------------------------------------------------------------
// Weight transpose: conv_w [co][ci][3][3] -> conv-ready layout (see g_wt2)
// co = t*64 + cg*4 + i
// ---------------------------------------------------------------------------
__global__ void wtrans_kernel(const float* __restrict__ w) {
    int idx = blockIdx.x * 256 + threadIdx.x;
    if (idx >= 589824) return;
    int co = idx / 2304;
    int rem = idx - co * 2304;       // ci*9 + k
    float v = w[idx];
    int t = co >> 6;
    int cg = (co & 63) >> 2;
    int i = co & 3;
    g_wt2[(size_t)((t * 2304 + rem) * 4 + i) * 16 + cg] = make_float2(v, v);
}

// ---------------------------------------------------------------------------
// Fused 3x3 conv + bias + ReLU over all levels.
// Block 512 thr. Tile: 64 co x (8 rows x 32 cols). Per-thread 4 co x 8 px.
// Double-buffered smem (cp.async): weights [2][4608]f2, XsE/XsS [2][8][10][34]f.
// grid.x = 8 * 342 (n,cot x tiles).
// ---------------------------------------------------------------------------
#define XS_ELEMS 2720   // 8*10*34
#define WS_ELEMS 4608   // 8*9*64 float2

struct ConvPtrs { const float* f[5]; };

__global__ __launch_bounds__(512, 1)
void conv_fused_kernel(ConvPtrs P, const float* __restrict__ bias) {
    const int b = blockIdx.x;
    const int nc = b / 342;
    const int t = b - nc * 342;
    const int n = nc >> 2, cot = nc & 3;
    int l = (t < 256) ? 0 : (t < 320) ? 1 : (t < 336) ? 2 : (t < 340) ? 3 : 4;
    const int r = t - c_TS[l];
    const int tc = c_TC[l];
    const int ty = r / tc, tx = r - ty * tc;
    const int W = c_LW[l], H = W;
    const int HW = H * W;
    const int x0 = tx * 32, y0 = ty * 8;
    const float* inb = P.f[l] + (size_t)n * 256 * HW;

    extern __shared__ __align__(16) char smem[];
    float2* Ws  = (float2*)smem;                       // [2][4608]
    float*  XsE = (float*)(smem + 2 * WS_ELEMS * 8);   // [2][2720]
    float*  XsS = XsE + 2 * XS_ELEMS;                  // [2][2720]

    const int tid = threadIdx.x;
    const int cg = tid & 15;
    const int pg = tid >> 4;          // 0..31
    const int row = pg >> 2;          // 0..7
    const int col8 = (pg & 3) * 8;    // 0,8,16,24

    const float2* wsrc = g_wt2 + (size_t)cot * 2304 * 64;

    // ---- staging lambda (cp.async) ----
    auto stage = [&](int iter, int buf) {
        const int ci0 = iter * 8;
        // weights: contiguous 4608 float2
        {
            const float2* src = wsrc + (size_t)ci0 * 9 * 64;
            u32 dst = s2u(Ws + buf * WS_ELEMS);
            for (int i = tid; i < WS_ELEMS; i += 512)
                cpa8(dst + i * 8, src + i);
        }
        // inputs: 2720 floats x 2 copies (even + shifted)
        {
            u32 de = s2u(XsE + buf * XS_ELEMS);
            u32 ds = s2u(XsS + buf * XS_ELEMS);
            for (int i = tid; i < XS_ELEMS; i += 512) {
                int ciq = i / 340;
                int rem = i - ciq * 340;
                int rr = rem / 34, cc = rem - rr * 34;
                int gy = y0 - 1 + rr;
                int gxE = x0 - 1 + cc;
                int gxS = x0 + cc;
                const float* gp = inb + (size_t)(ci0 + ciq) * HW + (size_t)gy * W;
                bool rowok = (gy >= 0) & (gy < H);
                bool okE = rowok & (gxE >= 0) & (gxE < W);
                bool okS = rowok & (gxS < W);
                cpa4z(de + i * 4, okE ? (gp + gxE) : inb, okE ? 4 : 0);
                cpa4z(ds + i * 4, okS ? (gp + gxS) : inb, okS ? 4 : 0);
            }
        }
    };

    u64 acc[4][4];
#pragma unroll
    for (int i = 0; i < 4; i++)
#pragma unroll
        for (int j = 0; j < 4; j++) acc[i][j] = 0ull;

    stage(0, 0); CPA_COMMIT();
    stage(1, 1); CPA_COMMIT();
    CPA_WAIT1();
    __syncthreads();

#pragma unroll 1
    for (int it = 0; it < 32; it++) {
        const int buf = it & 1;
        const u64* wp64 = (const u64*)(Ws + buf * WS_ELEMS);
        const float* xe0 = XsE + buf * XS_ELEMS;
        const float* xs0 = XsS + buf * XS_ELEMS;

#pragma unroll
        for (int ciq = 0; ciq < 8; ciq++) {
#pragma unroll
            for (int ky = 0; ky < 3; ky++) {
                const int xoff = (ciq * 10 + row + ky) * 34 + col8;
                const float* xe = xe0 + xoff;
                const float* xs = xs0 + xoff;
                u64 pe0 = *(const u64*)(xe);
                u64 pe1 = *(const u64*)(xe + 2);
                u64 pe2 = *(const u64*)(xe + 4);
                u64 pe3 = *(const u64*)(xe + 6);
                u64 pe4 = *(const u64*)(xe + 8);
                u64 po0 = *(const u64*)(xs);
                u64 po1 = *(const u64*)(xs + 2);
                u64 po2 = *(const u64*)(xs + 4);
                u64 po3 = *(const u64*)(xs + 6);
                const u64* wb = wp64 + (size_t)(ciq * 9 + ky * 3) * 64 + cg;
#pragma unroll
                for (int i = 0; i < 4; i++) {
                    u64 w = wb[i * 16];
                    FMA2(acc[i][0], w, pe0); FMA2(acc[i][1], w, pe1);
                    FMA2(acc[i][2], w, pe2); FMA2(acc[i][3], w, pe3);
                }
#pragma unroll
                for (int i = 0; i < 4; i++) {
                    u64 w = wb[64 + i * 16];
                    FMA2(acc[i][0], w, po0); FMA2(acc[i][1], w, po1);
                    FMA2(acc[i][2], w, po2); FMA2(acc[i][3], w, po3);
                }
#pragma unroll
                for (int i = 0; i < 4; i++) {
                    u64 w = wb[128 + i * 16];
                    FMA2(acc[i][0], w, pe1); FMA2(acc[i][1], w, pe2);
                    FMA2(acc[i][2], w, pe3); FMA2(acc[i][3], w, pe4);
                }
            }
        }

        __syncthreads();                    // all done reading buf before restage
        if (it + 2 < 32) stage(it + 2, buf);
        CPA_COMMIT();                       // (possibly empty) group
        CPA_WAIT1();                        // group for it+1 complete
        __syncthreads();
    }

    // epilogue: bias + relu, write 4 co x 8 px (guard partial tiles: level 4)
    if (x0 + col8 < W) {
#pragma unroll
        for (int i = 0; i < 4; i++) {
            int co = cot * 64 + cg * 4 + i;
            float bv = bias[co];
            float2 v0 = upk(acc[i][0]), v1 = upk(acc[i][1]), v2 = upk(acc[i][2]), v3 = upk(acc[i][3]);
            float4 o1, o2;
            o1.x = fmaxf(v0.x + bv, 0.f); o1.y = fmaxf(v0.y + bv, 0.f);
            o1.z = fmaxf(v1.x + bv, 0.f); o1.w = fmaxf(v1.y + bv, 0.f);
            o2.x = fmaxf(v2.x + bv, 0.f); o2.y = fmaxf(v2.y + bv, 0.f);
            o2.z = fmaxf(v3.x + bv, 0.f); o2.w = fmaxf(v3.y + bv, 0.f);
            float* dst = g_t + (size_t)(n * 256 + co) * TOTHW + c_HWOFF[l]
                       + (size_t)(y0 + row) * W + x0 + col8;
            *(float4*)dst = o1;
            *(float4*)(dst + 4) = o2;
        }
    }
}

// ---------------------------------------------------------------------------
// 1x1 heads: 3 obj + 12 delta channels -> combined output [n][Atot][5]
// ---------------------------------------------------------------------------
__global__ __launch_bounds__(256)
void head_kernel(const float* __restrict__ ow, const float* __restrict__ ob,
                 const float* __restrict__ dw, const float* __restrict__ db,
                 float* __restrict__ out, int hwoff, int aoff) {
    __shared__ float sW[15 * 256];
    int tid = threadIdx.x;
    for (int i = tid; i < 3840; i += 256) {
        int k = i >> 8, ci = i & 255;
        sW[i] = (k < 3) ? ow[k * 256 + ci] : dw[(k - 3) * 256 + ci];
    }
    __syncthreads();
    int n = blockIdx.z;
    int hw = blockIdx.x * 256 + tid;
    const float* tp = g_t + (size_t)n * 256 * TOTHW + hwoff + hw;
    float acc[15];
#pragma unroll
    for (int k = 0; k < 15; k++) acc[k] = (k < 3) ? ob[k] : db[k - 3];
    for (int ci = 0; ci < 256; ci++) {
        float v = tp[(size_t)ci * TOTHW];
#pragma unroll
        for (int k = 0; k < 15; k++) acc[k] += v * sW[k * 256 + ci];
    }
    float* o = out + ((size_t)n * ATOT + aoff) * 5 + (size_t)hw * 15;
#pragma unroll
    for (int a = 0; a < 3; a++) {
        o[a * 5] = acc[a];
#pragma unroll
        for (int cc = 0; cc < 4; cc++) o[a * 5 + 1 + cc] = acc[3 + a * 4 + cc];
    }
}

// ---------------------------------------------------------------------------
// keys for per-level topk sort
// ---------------------------------------------------------------------------
__global__ void key1_kernel(const float* __restrict__ out) {
    int i = blockIdx.x * 256 + threadIdx.x;
    if (i >= 2 * ATOT) return;
    int n = i / ATOT, g = i - n * ATOT;
    int l = lvl_of_g(g);
    float sc = out[(size_t)(n * ATOT + g) * 5];
    u32 u = __float_as_uint(sc);
    u32 m = u ^ (((int)u < 0) ? 0xFFFFFFFFu : 0x80000000u);
    u32 inv = ~m;
    int idx = g - c_AOFF[l];
    g_keys[i] = ((u64)(u32)(n * 5 + l) << 50) | ((u64)inv << 18) | (u32)idx;
}

// ---------------------------------------------------------------------------
// gather candidates: decode + clip, build NMS order keys
// ---------------------------------------------------------------------------
__global__ void cand_kernel(const float* __restrict__ out) {
    int t = blockIdx.x * 256 + threadIdx.x;
    if (t >= 2 * MCAND) return;
    int n = t / MCAND, c = t - n * MCAND;
    int l = lvl_of_c(c);
    int r = c - c_COFF[l];
    u64 key = g_keyso[(size_t)n * ATOT + c_AOFF[l] + r];
    int idx = (int)(key & 0x3FFFFull);
    int a = idx % 3;
    int hw = idx / 3;
    int W = c_LW[l];
    int py = hw / W, px = hw - py * W;

    double ratio = (a == 0) ? 0.5 : (a == 1) ? 1.0 : 2.0;
    double sz = (double)c_SZ[l];
    double ws = sqrt(sz * sz / ratio);
    double hs = ws * ratio;
    double xx = (double)(px * c_STR[l]);
    double yy = (double)(py * c_STR[l]);
    float ax1 = (float)(xx - ws * 0.5), ay1 = (float)(yy - hs * 0.5);
    float ax2 = (float)(xx + ws * 0.5), ay2 = (float)(yy + hs * 0.5);

    float aw = ax2 - ax1, ah = ay2 - ay1;
    float acx = ax1 + 0.5f * aw, acy = ay1 + 0.5f * ah;
    const float* cmb = out + (size_t)(n * ATOT + c_AOFF[l] + idx) * 5;
    float sc = cmb[0];
    float dx = cmb[1], dy = cmb[2];
    float dwv = fminf(cmb[3], SCALE_CLAMP);
    float dhv = fminf(cmb[4], SCALE_CLAMP);
    float pcx = dx * aw + acx, pcy = dy * ah + acy;
    float pw = expf(dwv) * aw, ph = expf(dhv) * ah;
    float x1 = pcx - 0.5f * pw, y1 = pcy - 0.5f * ph;
    float x2 = pcx + 0.5f * pw, y2 = pcy + 0.5f * ph;
    x1 = fminf(fmaxf(x1, 0.f), 1024.f);
    y1 = fminf(fmaxf(y1, 0.f), 1024.f);
    x2 = fminf(fmaxf(x2, 0.f), 1024.f);
    y2 = fminf(fmaxf(y2, 0.f), 1024.f);

    float* bp = g_boxes + (size_t)t * 4;
    bp[0] = x1; bp[1] = y1; bp[2] = x2; bp[3] = y2;
    g_scores[t] = sc;

    u32 u = __float_as_uint(sc);
    u32 m = u ^ (((int)u < 0) ? 0xFFFFFFFFu : 0x80000000u);
    u32 inv = ~m;
    g_k2[t] = ((u64)(u32)n << 47) | ((u64)inv << 15) | (u32)c;
}

// ---------------------------------------------------------------------------
// NMS suppression bitmask (level-block-diagonal, upper triangle, offset boxes)
// ---------------------------------------------------------------------------
__global__ __launch_bounds__(128)
void mask_kernel(int l) {
    int K = c_K[l], Wn = c_W32[l];
    int cb = blockIdx.x * 128, rb = blockIdx.y * 128;
    if (rb > cb + 127) return;
    int b = blockIdx.z;
    int tid = threadIdx.x;
    __shared__ float4 sB[128];
    __shared__ float sA[128];
    float off = (float)l * 2000.0f;

    int cc = cb + tid;
    if (cc < K) {
        const float* bp = g_boxes + ((size_t)b * MCAND + c_COFF[l] + cc) * 4;
        float4 v = make_float4(bp[0] + off, bp[1] + off, bp[2] + off, bp[3] + off);
        sB[tid] = v;
        sA[tid] = (v.z - v.x) * (v.w - v.y);
    }
    __syncthreads();
    int r = rb + tid;
    if (r >= K) return;
    const float* rp = g_boxes + ((size_t)b * MCAND + c_COFF[l] + r) * 4;
    float rx1 = rp[0] + off, ry1 = rp[1] + off, rx2 = rp[2] + off, ry2 = rp[3] + off;
    float ra = (rx2 - rx1) * (ry2 - ry1);
    u32 wds[4] = {0, 0, 0, 0};
    int jmax = min(128, K - cb);
    for (int j = 0; j < jmax; j++) {
        int c2 = cb + j;
        if (c2 <= r) continue;
        float4 o = sB[j];
        float x1 = fmaxf(rx1, o.x), y1 = fmaxf(ry1, o.y);
        float x2 = fminf(rx2, o.z), y2 = fminf(ry2, o.w);
        float inter = fmaxf(x2 - x1, 0.f) * fmaxf(y2 - y1, 0.f);
        float iou = inter / (ra + sA[j] - inter + 1e-9f);
        if (iou > NMS_T) wds[j >> 5] |= 1u << (j & 31);
    }
    u32* dst = g_mask + (size_t)b * MASK_PER_BATCH + c_MOFF[l] + (size_t)r * Wn + (cb >> 5);
#pragma unroll
    for (int w2 = 0; w2 < 4; w2++)
        if ((cb >> 5) + w2 < Wn) dst[w2] = wds[w2];
}

// ---------------------------------------------------------------------------
// Greedy scan: 1 warp per batch, removed-bitmap in smem, ballot skip
// ---------------------------------------------------------------------------
__global__ __launch_bounds__(32)
void scan_kernel(float* __restrict__ out) {
    int b = blockIdx.x;
    int lane = threadIdx.x;
    __shared__ u32 rem[REM_WORDS];
    for (int i = lane; i < REM_WORDS; i += 32) rem[i] = 0;
    __syncwarp();

    const u64* ord = g_k2o + (size_t)b * MCAND;
    int p = 0, kept = 0;
    while (p < MCAND && kept < POST_K) {
        int rank = p + lane;
        int c = -1;
        bool fr = false;
        if (rank < MCAND) {
            c = (int)(ord[rank] & 0x7FFFull);
            int l = lvl_of_c(c);
            int rl = c - c_COFF[l];
            fr = !((rem[c_RWOFF[l] + (rl >> 5)] >> (rl & 31)) & 1u);
        }
        u32 fm = __ballot_sync(0xffffffffu, fr);
        if (!fm) { p += 32; continue; }
        int tt = __ffs(fm) - 1;
        int ck = __shfl_sync(0xffffffffu, c, tt);
        int l = lvl_of_c(ck);
        int rl = ck - c_COFF[l];
        int Wn = c_W32[l];
        const u32* rowp = g_mask + (size_t)b * MASK_PER_BATCH + c_MOFF[l] + (size_t)rl * Wn;
        for (int w = lane; w < Wn; w += 32) rem[c_RWOFF[l] + w] |= rowp[w];
        if (lane == 0) {
            const float* bx = g_boxes + ((size_t)b * MCAND + ck) * 4;
            float* kb = out + OUT_KB + ((size_t)b * POST_K + kept) * 4;
            kb[0] = bx[0]; kb[1] = bx[1]; kb[2] = bx[2]; kb[3] = bx[3];
            out[OUT_KS + b * POST_K + kept] = g_scores[(size_t)b * MCAND + ck];
            out[OUT_VALID + b * POST_K + kept] = 1.0f;
        }
        __syncwarp();
        kept++;
        p = p + tt + 1;
    }
    const float* bx0 = g_boxes + (size_t)b * MCAND * 4;
    float s0 = g_scores[(size_t)b * MCAND];
    for (int k2 = kept + lane; k2 < POST_K; k2 += 32) {
        float* kb = out + OUT_KB + ((size_t)b * POST_K + k2) * 4;
        kb[0] = bx0[0]; kb[1] = bx0[1]; kb[2] = bx0[2]; kb[3] = bx0[3];
        out[OUT_KS + b * POST_K + k2] = s0;
        out[OUT_VALID + b * POST_K + k2] = 0.0f;
    }
}

// ---------------------------------------------------------------------------
// Host launcher
// ---------------------------------------------------------------------------
extern "C" void kernel_launch(void* const* d_in, const int* in_sizes, int n_in,
                              void* d_out, int out_size) {
    const float* conv_w = (const float*)d_in[5];
    const float* conv_b = (const float*)d_in[6];
    const float* obj_w  = (const float*)d_in[7];
    const float* obj_b  = (const float*)d_in[8];
    const float* del_w  = (const float*)d_in[9];
    const float* del_b  = (const float*)d_in[10];
    float* out = (float*)d_out;

    static const int hHW[5] = {65536, 16384, 4096, 1024, 256};
    static const int hHWOFF[5] = {0, 65536, 81920, 86016, 87040};
    static const int hAOFF[5] = {0, 196608, 245760, 258048, 261120};
    static const int hT[5] = {47, 47, 47, 24, 6};

    void *p_keys, *p_keyso, *p_k2, *p_k2o, *p_mask, *p_tmp;
    cudaGetSymbolAddress(&p_keys, g_keys);
    cudaGetSymbolAddress(&p_keyso, g_keyso);
    cudaGetSymbolAddress(&p_k2, g_k2);
    cudaGetSymbolAddress(&p_k2o, g_k2o);
    cudaGetSymbolAddress(&p_mask, g_mask);
    cudaGetSymbolAddress(&p_tmp, g_cubtmp);

    wtrans_kernel<<<2304, 256>>>(conv_w);

    // fused conv over all levels
    {
        ConvPtrs P;
        for (int i = 0; i < 5; i++) P.f[i] = (const float*)d_in[i];
        int smem = 2 * WS_ELEMS * 8 + 2 * 2 * XS_ELEMS * 4;   // 117,248 B
        static int configured = 0;
        if (!configured) {
            cudaFuncSetAttribute(conv_fused_kernel,
                                 cudaFuncAttributeMaxDynamicSharedMemorySize, smem);
            configured = 1;
        }
        conv_fused_kernel<<<8 * 342, 512, smem>>>(P, conv_b);
    }

    for (int l = 0; l < 5; l++) {
        dim3 g(hHW[l] / 256, 1, 2);
        head_kernel<<<g, 256>>>(obj_w, obj_b, del_w, del_b, out, hHWOFF[l], hAOFF[l]);
    }

    key1_kernel<<<(2 * ATOT) / 256, 256>>>(out);
    {
        size_t tb = sizeof(g_cubtmp);
        cub::DeviceRadixSort::SortKeys(p_tmp, tb, (const u64*)p_keys, (u64*)p_keyso,
                                       2 * ATOT, 0, 54);
    }

    cand_kernel<<<(2 * MCAND + 255) / 256, 256>>>(out);
    {
        size_t tb = sizeof(g_cubtmp);
        cub::DeviceRadixSort::SortKeys(p_tmp, tb, (const u64*)p_k2, (u64*)p_k2o,
                                       2 * MCAND, 0, 48);
    }

    cudaMemsetAsync(p_mask, 0, (size_t)2 * MASK_PER_BATCH * sizeof(u32));
    for (int l = 0; l < 5; l++) {
        dim3 g(hT[l], hT[l], 2);
        mask_kernel<<<g, 128>>>(l);
    }

    scan_kernel<<<2, 32>>>(out);
}

// round 5
// speedup vs baseline: 1.6045x; 1.0273x over previous
#include <cuda_runtime.h>
#include <cuda_bf16.h>
#include <cub/cub.cuh>
#include <cstdint>
#include <math.h>

typedef unsigned long long u64;
typedef unsigned int u32;

// ---------------------------------------------------------------------------
// Problem constants
// ---------------------------------------------------------------------------
#define NLVL 5
#define ATOT 261888          // total anchors per image
#define MCAND 21840          // total NMS candidates per image
#define POST_K 1000
#define NMS_T 0.7f
#define SCALE_CLAMP 4.135166556742356f
#define TOTHW 87296
#define MASK_PER_BATCH 3697344   // u32 words per batch
#define REM_WORDS 684

// output layout (float32)
#define OUT_KB   2618880
#define OUT_KS   2626880
#define OUT_VALID 2628880

__constant__ int c_COFF[5]  = {0, 6000, 12000, 18000, 21072};
__constant__ int c_K[5]     = {6000, 6000, 6000, 3072, 768};
__constant__ int c_W32[5]   = {188, 188, 188, 96, 24};
__constant__ int c_RWOFF[5] = {0, 188, 376, 564, 660};
__constant__ int c_MOFF[5]  = {0, 1128000, 2256000, 3384000, 3678912};
__constant__ int c_AOFF[5]  = {0, 196608, 245760, 258048, 261120};
__constant__ int c_LW[5]    = {256, 128, 64, 32, 16};
__constant__ int c_STR[5]   = {4, 8, 16, 32, 64};
__constant__ int c_SZ[5]    = {32, 64, 128, 256, 512};

// fused-conv tile table
__constant__ int c_TS[6]    = {0, 256, 320, 336, 340, 342}; // tile start per level
__constant__ int c_TC[5]    = {8, 4, 2, 1, 1};              // tile cols per level
__constant__ int c_HWOFF[5] = {0, 65536, 81920, 86016, 87040};

// ---------------------------------------------------------------------------
// Static device scratch
// ---------------------------------------------------------------------------
__device__ float  g_t[2u * 256u * TOTHW];          // conv outputs (relu'd), [n][ci][TOTHW]
// weights, conv-ready: float4 index = (cot*2304 + ci*9 + k)*32 + p*16 + cg,
// float4 = {w(i=2p),w(i=2p),w(i=2p+1),w(i=2p+1)}, co = cot*64 + cg*4 + i
__device__ float  g_wtf[1179648];
__device__ u64    g_keys[2 * ATOT];
__device__ u64    g_keyso[2 * ATOT];
__device__ float  g_boxes[2 * MCAND * 4];
__device__ float  g_scores[2 * MCAND];
__device__ u64    g_k2[2 * MCAND];
__device__ u64    g_k2o[2 * MCAND];
__device__ u32    g_mask[2u * MASK_PER_BATCH];
__device__ unsigned char g_cubtmp[48u * 1024u * 1024u];

__device__ __forceinline__ int lvl_of_c(int c) {
    return (c < 6000) ? 0 : (c < 12000) ? 1 : (c < 18000) ? 2 : (c < 21072) ? 3 : 4;
}
__device__ __forceinline__ int lvl_of_g(int g) {
    return (g < 196608) ? 0 : (g < 245760) ? 1 : (g < 258048) ? 2 : (g < 261120) ? 3 : 4;
}

// f32x2 helpers
__device__ __forceinline__ u64 pk(float lo, float hi) {
    u64 r; asm("mov.b64 %0, {%1,%2};" : "=l"(r) : "f"(lo), "f"(hi)); return r;
}
__device__ __forceinline__ float2 upk(u64 v) {
    float2 r; asm("mov.b64 {%0,%1}, %2;" : "=f"(r.x), "=f"(r.y) : "l"(v)); return r;
}
#define FMA2(d, a, b) asm("fma.rn.f32x2 %0, %1, %2, %0;" : "+l"(d) : "l"(a), "l"(b))

// cp.async helpers
__device__ __forceinline__ u32 s2u(const void* p) { return (u32)__cvta_generic_to_shared(p); }
__device__ __forceinline__ void cpa16(u32 d, const void* s) {
    asm volatile("cp.async.cg.shared.global [%0], [%1], 16;" :: "r"(d), "l"(s));
}
__device__ __forceinline__ void cpa4z(u32 d, const void* s, int sz) {
    asm volatile("cp.async.ca.shared.global [%0], [%1], 4, %2;" :: "r"(d), "l"(s), "r"(sz));
}
#define CPA_COMMIT() asm volatile("cp.async.commit_group;")
#define CPA_WAIT1()  asm volatile("cp.async.wait_group 1;")

__device__ __forceinline__ void pref_l2(const void* p) {
    asm volatile("prefetch.global.L2 [%0];" :: "l"(p));
}

// ---------------------------------------------------------------------------
// Weight transpose: conv_w [co][ci][3][3] -> conv-ready layout (see g_wtf)
// ---------------------------------------------------------------------------
__global__ void wtrans_kernel(const float* __restrict__ w) {
    int idx = blockIdx.x * 256 + threadIdx.x;
    if (idx >= 589824) return;
    int co = idx / 2304;
    int rem = idx - co * 2304;       // ci*9 + k
    float v = w[idx];
    int t = co >> 6;
    int cg = (co >> 2) & 15;
    int i = co & 3;
    int p = i >> 1, h = i & 1;
    float* dst = g_wtf + (size_t)(((t * 2304 + rem) * 2 + p) * 16 + cg) * 4 + h * 2;
    dst[0] = v; dst[1] = v;
}

// ---------------------------------------------------------------------------
// Fused 3x3 conv + bias + ReLU over all levels.
// Block 512 thr. Tile: 64 co x (8 rows x 32 cols). Per-thread 4 co x 8 px.
// Triple-buffered smem (cp.async), one barrier per iteration.
// ---------------------------------------------------------------------------
#define XS_ROW 36
#define XS_ELEMS 2880   // 8*10*36
#define WS_F4 2304      // 8ci * 9k * 2p * 16cg float4

struct ConvPtrs { const float* f[5]; };

__global__ __launch_bounds__(512, 1)
void conv_fused_kernel(ConvPtrs P, const float* __restrict__ bias) {
    const int b = blockIdx.x;
    const int nc = b / 342;
    const int t = b - nc * 342;
    const int n = nc >> 2, cot = nc & 3;
    int l = (t < 256) ? 0 : (t < 320) ? 1 : (t < 336) ? 2 : (t < 340) ? 3 : 4;
    const int r = t - c_TS[l];
    const int tc = c_TC[l];
    const int ty = r / tc, tx = r - ty * tc;
    const int W = c_LW[l], H = W;
    const int HW = H * W;
    const int x0 = tx * 32, y0 = ty * 8;
    const float* inb = P.f[l] + (size_t)n * 256 * HW;

    extern __shared__ __align__(16) char smem[];
    float4* Ws = (float4*)smem;                        // [3][2304]
    float*  XE = (float*)(smem + 3 * WS_F4 * 16);      // [3][2880]
    float*  XS = XE + 3 * XS_ELEMS;                    // [3][2880]

    const int tid = threadIdx.x;
    const int cg = tid & 15;
    const int pg = tid >> 4;          // 0..31
    const int row = pg >> 2;          // 0..7
    const int col8 = (pg & 3) * 8;    // 0,8,16,24

    const float4* wsrc4 = (const float4*)g_wtf + (size_t)cot * 2304 * 32;

    auto stage = [&](int iter, int buf) {
        const int ci0 = iter * 8;
        // weights: 2304 contiguous float4
        {
            const float4* src = wsrc4 + (size_t)ci0 * 9 * 32;
            u32 dst = s2u(Ws + buf * WS_F4);
            for (int i = tid; i < WS_F4; i += 512) cpa16(dst + i * 16, src + i);
        }
        // inputs: E (x0-1 base) and S (x0 base) copies, rows of 36 (34 used)
        {
            u32 de = s2u(XE + buf * XS_ELEMS);
            u32 ds = s2u(XS + buf * XS_ELEMS);
            for (int i = tid; i < XS_ELEMS; i += 512) {
                int rr2 = i / XS_ROW;
                int cc = i - rr2 * XS_ROW;
                if (cc < 34) {
                    int ciq = rr2 / 10, rr = rr2 - ciq * 10;
                    int gy = y0 - 1 + rr;
                    int gxE = x0 - 1 + cc;
                    int gxS = x0 + cc;
                    const float* gp = inb + (size_t)(ci0 + ciq) * HW + (size_t)gy * W;
                    bool rowok = (gy >= 0) & (gy < H);
                    bool okE = rowok & (gxE >= 0) & (gxE < W);
                    bool okS = rowok & (gxS < W);
                    cpa4z(de + i * 4, okE ? (gp + gxE) : inb, okE ? 4 : 0);
                    cpa4z(ds + i * 4, okS ? (gp + gxS) : inb, okS ? 4 : 0);
                }
            }
        }
    };

    u64 acc[4][4];
#pragma unroll
    for (int i = 0; i < 4; i++)
#pragma unroll
        for (int j = 0; j < 4; j++) acc[i][j] = 0ull;

    stage(0, 0); CPA_COMMIT();
    stage(1, 1); CPA_COMMIT();
    CPA_WAIT1();
    __syncthreads();

#define Q4(i, w, a0, a1, a2, a3) \
    FMA2(acc[i][0], w, a0); FMA2(acc[i][1], w, a1); \
    FMA2(acc[i][2], w, a2); FMA2(acc[i][3], w, a3)

    int buf = 0;
#pragma unroll 1
    for (int it = 0; it < 32; it++) {
        const float4* Wb = Ws + buf * WS_F4;
        const float* XEb = XE + buf * XS_ELEMS;
        const float* XSb = XS + buf * XS_ELEMS;

#pragma unroll 1
        for (int hlf = 0; hlf < 2; hlf++) {
#pragma unroll
            for (int cq = 0; cq < 4; cq++) {
                int ciq = hlf * 4 + cq;
#pragma unroll
                for (int ky = 0; ky < 3; ky++) {
                    const int xoff = (ciq * 10 + row + ky) * XS_ROW + col8;
                    const float* xe = XEb + xoff;
                    const float* xs = XSb + xoff;
                    ulonglong2 E0 = *(const ulonglong2*)xe;       // pe0 pe1
                    ulonglong2 E1 = *(const ulonglong2*)(xe + 4); // pe2 pe3
                    u64 pe4 = *(const u64*)(xe + 8);
                    ulonglong2 S0 = *(const ulonglong2*)xs;       // ps0 ps1
                    ulonglong2 S1 = *(const ulonglong2*)(xs + 4); // ps2 ps3
                    const float4* wk = Wb + (size_t)((ciq * 9 + ky * 3) * 2) * 16 + cg;
                    float4 w0a = wk[0],  w0b = wk[16];
                    float4 w1a = wk[32], w1b = wk[48];
                    float4 w2a = wk[64], w2b = wk[80];
                    u64 wl, wh;
                    // kx = 0
                    wl = pk(w0a.x, w0a.y); wh = pk(w0a.z, w0a.w);
                    Q4(0, wl, E0.x, E0.y, E1.x, E1.y);
                    Q4(1, wh, E0.x, E0.y, E1.x, E1.y);
                    wl = pk(w0b.x, w0b.y); wh = pk(w0b.z, w0b.w);
                    Q4(2, wl, E0.x, E0.y, E1.x, E1.y);
                    Q4(3, wh, E0.x, E0.y, E1.x, E1.y);
                    // kx = 1
                    wl = pk(w1a.x, w1a.y); wh = pk(w1a.z, w1a.w);
                    Q4(0, wl, S0.x, S0.y, S1.x, S1.y);
                    Q4(1, wh, S0.x, S0.y, S1.x, S1.y);
                    wl = pk(w1b.x, w1b.y); wh = pk(w1b.z, w1b.w);
                    Q4(2, wl, S0.x, S0.y, S1.x, S1.y);
                    Q4(3, wh, S0.x, S0.y, S1.x, S1.y);
                    // kx = 2
                    wl = pk(w2a.x, w2a.y); wh = pk(w2a.z, w2a.w);
                    Q4(0, wl, E0.y, E1.x, E1.y, pe4);
                    Q4(1, wh, E0.y, E1.x, E1.y, pe4);
                    wl = pk(w2b.x, w2b.y); wh = pk(w2b.z, w2b.w);
                    Q4(2, wl, E0.y, E1.x, E1.y, pe4);
                    Q4(3, wh, E0.y, E1.x, E1.y, pe4);
                }
            }
        }

        if (it + 2 < 32) {
            int nb = it + 2;
            stage(nb, nb - (nb / 3) * 3);
        }
        CPA_COMMIT();
        CPA_WAIT1();
        __syncthreads();
        buf++; if (buf == 3) buf = 0;
    }
#undef Q4

    // epilogue: bias + relu, write 4 co x 8 px (guard partial tiles)
    if (x0 + col8 < W) {
#pragma unroll
        for (int i = 0; i < 4; i++) {
            int co = cot * 64 + cg * 4 + i;
            float bv = bias[co];
            float2 v0 = upk(acc[i][0]), v1 = upk(acc[i][1]), v2 = upk(acc[i][2]), v3 = upk(acc[i][3]);
            float4 o1, o2;
            o1.x = fmaxf(v0.x + bv, 0.f); o1.y = fmaxf(v0.y + bv, 0.f);
            o1.z = fmaxf(v1.x + bv, 0.f); o1.w = fmaxf(v1.y + bv, 0.f);
            o2.x = fmaxf(v2.x + bv, 0.f); o2.y = fmaxf(v2.y + bv, 0.f);
            o2.z = fmaxf(v3.x + bv, 0.f); o2.w = fmaxf(v3.y + bv, 0.f);
            float* dst = g_t + (size_t)(n * 256 + co) * TOTHW + c_HWOFF[l]
                       + (size_t)(y0 + row) * W + x0 + col8;
            *(float4*)dst = o1;
            *(float4*)(dst + 4) = o2;
        }
    }
}

// ---------------------------------------------------------------------------
// Fused 1x1 heads: one launch, 4 px/thread via float4, all levels.
// grid (86, 1, 2): blocks 0-63 lvl0, 64-79 lvl1, 80-83 lvl2, 84 lvl3, 85 lvl4
// ---------------------------------------------------------------------------
__global__ __launch_bounds__(256)
void head_fused_kernel(const float* __restrict__ ow, const float* __restrict__ ob,
                       const float* __restrict__ dw, const float* __restrict__ db,
                       float* __restrict__ out) {
    __shared__ float sW[15 * 256];
    int tid = threadIdx.x;
    for (int i = tid; i < 3840; i += 256) {
        int k = i >> 8, ci = i & 255;
        sW[i] = (k < 3) ? ow[k * 256 + ci] : dw[(k - 3) * 256 + ci];
    }
    __syncthreads();
    int b = blockIdx.x, n = blockIdx.z;
    int l, hw0, cnt = 1024;
    if (b < 64)      { l = 0; hw0 = b << 10; }
    else if (b < 80) { l = 1; hw0 = (b - 64) << 10; }
    else if (b < 84) { l = 2; hw0 = (b - 80) << 10; }
    else if (b == 84){ l = 3; hw0 = 0; }
    else             { l = 4; hw0 = 0; cnt = 256; }
    if (tid * 4 >= cnt) return;
    int px = hw0 + tid * 4;
    const float* tp = g_t + (size_t)n * 256 * TOTHW + c_HWOFF[l] + px;

    float acc[15][4];
#pragma unroll
    for (int k = 0; k < 15; k++) {
        float bv = (k < 3) ? ob[k] : db[k - 3];
        acc[k][0] = bv; acc[k][1] = bv; acc[k][2] = bv; acc[k][3] = bv;
    }
#pragma unroll 1
    for (int ci = 0; ci < 256; ci += 2) {
        float4 v0 = *(const float4*)(tp + (size_t)ci * TOTHW);
        float4 v1 = *(const float4*)(tp + (size_t)(ci + 1) * TOTHW);
#pragma unroll
        for (int k = 0; k < 15; k++) {
            float w0 = sW[k * 256 + ci], w1 = sW[k * 256 + ci + 1];
            acc[k][0] = fmaf(v0.x, w0, acc[k][0]); acc[k][0] = fmaf(v1.x, w1, acc[k][0]);
            acc[k][1] = fmaf(v0.y, w0, acc[k][1]); acc[k][1] = fmaf(v1.y, w1, acc[k][1]);
            acc[k][2] = fmaf(v0.z, w0, acc[k][2]); acc[k][2] = fmaf(v1.z, w1, acc[k][2]);
            acc[k][3] = fmaf(v0.w, w0, acc[k][3]); acc[k][3] = fmaf(v1.w, w1, acc[k][3]);
        }
    }
    float* o = out + ((size_t)n * ATOT + c_AOFF[l]) * 5 + (size_t)px * 15;
#pragma unroll
    for (int j = 0; j < 4; j++) {
        float* oj = o + j * 15;
#pragma unroll
        for (int a = 0; a < 3; a++) {
            oj[a * 5] = acc[a][j];
#pragma unroll
            for (int cc = 0; cc < 4; cc++) oj[a * 5 + 1 + cc] = acc[3 + a * 4 + cc][j];
        }
    }
}

// ---------------------------------------------------------------------------
// keys for per-level topk sort
// ---------------------------------------------------------------------------
__global__ void key1_kernel(const float* __restrict__ out) {
    int i = blockIdx.x * 256 + threadIdx.x;
    if (i >= 2 * ATOT) return;
    int n = i / ATOT, g = i - n * ATOT;
    int l = lvl_of_g(g);
    float sc = out[(size_t)(n * ATOT + g) * 5];
    u32 u = __float_as_uint(sc);
    u32 m = u ^ (((int)u < 0) ? 0xFFFFFFFFu : 0x80000000u);
    u32 inv = ~m;
    int idx = g - c_AOFF[l];
    g_keys[i] = ((u64)(u32)(n * 5 + l) << 50) | ((u64)inv << 18) | (u32)idx;
}

// ---------------------------------------------------------------------------
// gather candidates: decode + clip, build NMS order keys
// ---------------------------------------------------------------------------
__global__ void cand_kernel(const float* __restrict__ out) {
    int t = blockIdx.x * 256 + threadIdx.x;
    if (t >= 2 * MCAND) return;
    int n = t / MCAND, c = t - n * MCAND;
    int l = lvl_of_c(c);
    int r = c - c_COFF[l];
    u64 key = g_keyso[(size_t)n * ATOT + c_AOFF[l] + r];
    int idx = (int)(key & 0x3FFFFull);
    int a = idx % 3;
    int hw = idx / 3;
    int W = c_LW[l];
    int py = hw / W, px = hw - py * W;

    double ratio = (a == 0) ? 0.5 : (a == 1) ? 1.0 : 2.0;
    double sz = (double)c_SZ[l];
    double ws = sqrt(sz * sz / ratio);
    double hs = ws * ratio;
    double xx = (double)(px * c_STR[l]);
    double yy = (double)(py * c_STR[l]);
    float ax1 = (float)(xx - ws * 0.5), ay1 = (float)(yy - hs * 0.5);
    float ax2 = (float)(xx + ws * 0.5), ay2 = (float)(yy + hs * 0.5);

    float aw = ax2 - ax1, ah = ay2 - ay1;
    float acx = ax1 + 0.5f * aw, acy = ay1 + 0.5f * ah;
    const float* cmb = out + (size_t)(n * ATOT + c_AOFF[l] + idx) * 5;
    float sc = cmb[0];
    float dx = cmb[1], dy = cmb[2];
    float dwv = fminf(cmb[3], SCALE_CLAMP);
    float dhv = fminf(cmb[4], SCALE_CLAMP);
    float pcx = dx * aw + acx, pcy = dy * ah + acy;
    float pw = expf(dwv) * aw, ph = expf(dhv) * ah;
    float x1 = pcx - 0.5f * pw, y1 = pcy - 0.5f * ph;
    float x2 = pcx + 0.5f * pw, y2 = pcy + 0.5f * ph;
    x1 = fminf(fmaxf(x1, 0.f), 1024.f);
    y1 = fminf(fmaxf(y1, 0.f), 1024.f);
    x2 = fminf(fmaxf(x2, 0.f), 1024.f);
    y2 = fminf(fmaxf(y2, 0.f), 1024.f);

    float* bp = g_boxes + (size_t)t * 4;
    bp[0] = x1; bp[1] = y1; bp[2] = x2; bp[3] = y2;
    g_scores[t] = sc;

    u32 u = __float_as_uint(sc);
    u32 m = u ^ (((int)u < 0) ? 0xFFFFFFFFu : 0x80000000u);
    u32 inv = ~m;
    g_k2[t] = ((u64)(u32)n << 47) | ((u64)inv << 15) | (u32)c;
}

// ---------------------------------------------------------------------------
// NMS suppression bitmask (level-block-diagonal, upper triangle, offset boxes)
// ---------------------------------------------------------------------------
__global__ __launch_bounds__(128)
void mask_kernel(int l) {
    int K = c_K[l], Wn = c_W32[l];
    int cb = blockIdx.x * 128, rb = blockIdx.y * 128;
    if (rb > cb + 127) return;
    int b = blockIdx.z;
    int tid = threadIdx.x;
    __shared__ float4 sB[128];
    __shared__ float sA[128];
    float off = (float)l * 2000.0f;

    int cc = cb + tid;
    if (cc < K) {
        const float* bp = g_boxes + ((size_t)b * MCAND + c_COFF[l] + cc) * 4;
        float4 v = make_float4(bp[0] + off, bp[1] + off, bp[2] + off, bp[3] + off);
        sB[tid] = v;
        sA[tid] = (v.z - v.x) * (v.w - v.y);
    }
    __syncthreads();
    int r = rb + tid;
    if (r >= K) return;
    const float* rp = g_boxes + ((size_t)b * MCAND + c_COFF[l] + r) * 4;
    float rx1 = rp[0] + off, ry1 = rp[1] + off, rx2 = rp[2] + off, ry2 = rp[3] + off;
    float ra = (rx2 - rx1) * (ry2 - ry1);
    u32 wds[4] = {0, 0, 0, 0};
    int jmax = min(128, K - cb);
    for (int j = 0; j < jmax; j++) {
        int c2 = cb + j;
        if (c2 <= r) continue;
        float4 o = sB[j];
        float x1 = fmaxf(rx1, o.x), y1 = fmaxf(ry1, o.y);
        float x2 = fminf(rx2, o.z), y2 = fminf(ry2, o.w);
        float inter = fmaxf(x2 - x1, 0.f) * fmaxf(y2 - y1, 0.f);
        float iou = inter / (ra + sA[j] - inter + 1e-9f);
        if (iou > NMS_T) wds[j >> 5] |= 1u << (j & 31);
    }
    u32* dst = g_mask + (size_t)b * MASK_PER_BATCH + c_MOFF[l] + (size_t)r * Wn + (cb >> 5);
#pragma unroll
    for (int w2 = 0; w2 < 4; w2++)
        if ((cb >> 5) + w2 < Wn) dst[w2] = wds[w2];
}

// ---------------------------------------------------------------------------
// Greedy scan: 1 warp per batch, removed-bitmap in smem, ballot skip,
// L2 prefetch of likely-next mask row.
// ---------------------------------------------------------------------------
__global__ __launch_bounds__(32)
void scan_kernel(float* __restrict__ out) {
    int b = blockIdx.x;
    int lane = threadIdx.x;
    __shared__ u32 rem[REM_WORDS];
    for (int i = lane; i < REM_WORDS; i += 32) rem[i] = 0;
    __syncwarp();

    const u64* ord = g_k2o + (size_t)b * MCAND;
    int p = 0, kept = 0;
    while (p < MCAND && kept < POST_K) {
        int rank = p + lane;
        int c = -1;
        bool fr = false;
        if (rank < MCAND) {
            c = (int)(ord[rank] & 0x7FFFull);
            int l = lvl_of_c(c);
            int rl = c - c_COFF[l];
            fr = !((rem[c_RWOFF[l] + (rl >> 5)] >> (rl & 31)) & 1u);
        }
        // lookahead prefetch for ord stream
        if (p + 32 + lane * 8 < MCAND) pref_l2(&ord[p + 32 + lane * 8]);
        u32 fm = __ballot_sync(0xffffffffu, fr);
        if (!fm) { p += 32; continue; }
        int tt = __ffs(fm) - 1;
        int ck = __shfl_sync(0xffffffffu, c, tt);
        // prefetch second candidate's row (likely next pick)
        u32 fm2 = fm & (fm - 1);
        if (fm2) {
            int t2 = __ffs(fm2) - 1;
            int c2 = __shfl_sync(0xffffffffu, c, t2);
            int l2 = lvl_of_c(c2);
            int rl2 = c2 - c_COFF[l2];
            int Wn2 = c_W32[l2];
            const u32* rp2 = g_mask + (size_t)b * MASK_PER_BATCH + c_MOFF[l2] + (size_t)rl2 * Wn2;
            if (lane * 32 < Wn2) pref_l2(rp2 + lane * 32);
        }
        int l = lvl_of_c(ck);
        int rl = ck - c_COFF[l];
        int Wn = c_W32[l];
        const u32* rowp = g_mask + (size_t)b * MASK_PER_BATCH + c_MOFF[l] + (size_t)rl * Wn;
        for (int w = lane; w < Wn; w += 32) rem[c_RWOFF[l] + w] |= rowp[w];
        if (lane == 0) {
            const float* bx = g_boxes + ((size_t)b * MCAND + ck) * 4;
            float* kb = out + OUT_KB + ((size_t)b * POST_K + kept) * 4;
            kb[0] = bx[0]; kb[1] = bx[1]; kb[2] = bx[2]; kb[3] = bx[3];
            out[OUT_KS + b * POST_K + kept] = g_scores[(size_t)b * MCAND + ck];
            out[OUT_VALID + b * POST_K + kept] = 1.0f;
        }
        __syncwarp();
        kept++;
        p = p + tt + 1;
    }
    const float* bx0 = g_boxes + (size_t)b * MCAND * 4;
    float s0 = g_scores[(size_t)b * MCAND];
    for (int k2 = kept + lane; k2 < POST_K; k2 += 32) {
        float* kb = out + OUT_KB + ((size_t)b * POST_K + k2) * 4;
        kb[0] = bx0[0]; kb[1] = bx0[1]; kb[2] = bx0[2]; kb[3] = bx0[3];
        out[OUT_KS + b * POST_K + k2] = s0;
        out[OUT_VALID + b * POST_K + k2] = 0.0f;
    }
}

// ---------------------------------------------------------------------------
// Host launcher
// ---------------------------------------------------------------------------
extern "C" void kernel_launch(void* const* d_in, const int* in_sizes, int n_in,
                              void* d_out, int out_size) {
    const float* conv_w = (const float*)d_in[5];
    const float* conv_b = (const float*)d_in[6];
    const float* obj_w  = (const float*)d_in[7];
    const float* obj_b  = (const float*)d_in[8];
    const float* del_w  = (const float*)d_in[9];
    const float* del_b  = (const float*)d_in[10];
    float* out = (float*)d_out;

    static const int hT[5] = {47, 47, 47, 24, 6};

    void *p_keys, *p_keyso, *p_k2, *p_k2o, *p_mask, *p_tmp;
    cudaGetSymbolAddress(&p_keys, g_keys);
    cudaGetSymbolAddress(&p_keyso, g_keyso);
    cudaGetSymbolAddress(&p_k2, g_k2);
    cudaGetSymbolAddress(&p_k2o, g_k2o);
    cudaGetSymbolAddress(&p_mask, g_mask);
    cudaGetSymbolAddress(&p_tmp, g_cubtmp);

    cudaMemsetAsync(p_mask, 0, (size_t)2 * MASK_PER_BATCH * sizeof(u32));
    wtrans_kernel<<<2304, 256>>>(conv_w);

    // fused conv over all levels
    {
        ConvPtrs P;
        for (int i = 0; i < 5; i++) P.f[i] = (const float*)d_in[i];
        int smem = 3 * WS_F4 * 16 + 2 * 3 * XS_ELEMS * 4;   // 179,712 B
        static int configured = 0;
        if (!configured) {
            cudaFuncSetAttribute(conv_fused_kernel,
                                 cudaFuncAttributeMaxDynamicSharedMemorySize, smem);
            configured = 1;
        }
        conv_fused_kernel<<<8 * 342, 512, smem>>>(P, conv_b);
    }

    head_fused_kernel<<<dim3(86, 1, 2), 256>>>(obj_w, obj_b, del_w, del_b, out);

    key1_kernel<<<(2 * ATOT) / 256, 256>>>(out);
    {
        size_t tb = sizeof(g_cubtmp);
        cub::DeviceRadixSort::SortKeys(p_tmp, tb, (const u64*)p_keys, (u64*)p_keyso,
                                       2 * ATOT, 0, 54);
    }

    cand_kernel<<<(2 * MCAND + 255) / 256, 256>>>(out);
    {
        size_t tb = sizeof(g_cubtmp);
        cub::DeviceRadixSort::SortKeys(p_tmp, tb, (const u64*)p_k2, (u64*)p_k2o,
                                       2 * MCAND, 0, 48);
    }

    for (int l = 0; l < 5; l++) {
        dim3 g(hT[l], hT[l], 2);
        mask_kernel<<<g, 128>>>(l);
    }

    scan_kernel<<<2, 32>>>(out);
}